// round 1
// baseline (speedup 1.0000x reference)
#include <cuda_runtime.h>
#include <math.h>

// ---------------- problem constants (fixed shapes) ----------------
#define BSZ 32768
#define DM  1024
#define NHD 8
#define HD  128
#define HIDM 1024            // NHD*HD
#define KSZ 4
#define EPSV 1e-6f
#define CAPV 15.0f

// ---------------- scratch (static device globals; no allocs) ------
__device__ float g_Wcz[2 * DM * DM];                 // [2048,1024]: rows 0..1023 conv last tap, 1024..2047 z_w
__device__ float g_xconv[(size_t)BSZ * DM];          // SiLU(conv) activations
__device__ float g_z[(size_t)BSZ * HIDM];            // z projection
__device__ float g_hnorm[(size_t)BSZ * HIDM];        // normalized hidden
__device__ float g_ig[BSZ * NHD];
__device__ float g_fg[BSZ * NHD];
__device__ float g_og[BSZ * NHD];

// ---------------- weight packing ----------------------------------
__global__ void pack_w_kernel(const float* __restrict__ conv_w,
                              const float* __restrict__ z_w) {
    int idx = blockIdx.x * blockDim.x + threadIdx.x;
    if (idx < DM * DM) {
        int o = idx / DM, i = idx - o * DM;
        g_Wcz[idx] = conv_w[(o * DM + i) * KSZ + (KSZ - 1)];
    } else if (idx < 2 * DM * DM) {
        g_Wcz[idx] = z_w[idx - DM * DM];
    }
}

// ---------------- 128x128x16 SGEMM, 256 thr, 8x8 microtile --------
// C[M,N] = A[M,K] * W[N,K]^T
// MODE 0: A = inputs, W = g_Wcz (N=2048). Epilogue: cols<DM -> silu(+conv_b) -> g_xconv,
//         cols>=DM -> g_z.
// MODE 1: A = g_hnorm, W = out_w (N=1024). Epilogue: plain store to out.
template <int MODE>
__global__ __launch_bounds__(256) void gemm128_kernel(
    const float* __restrict__ A_in, const float* __restrict__ W_in,
    const float* __restrict__ bias, float* __restrict__ out_primary) {
    const float* A = (MODE == 1) ? (const float*)g_hnorm : A_in;
    const float* W = (MODE == 0) ? (const float*)g_Wcz : W_in;

    __shared__ float As[16][132];
    __shared__ float Bs[16][132];

    const int t   = threadIdx.x;
    const int bm0 = blockIdx.y * 128;
    const int bn0 = blockIdx.x * 128;
    const int tm  = (t >> 4) * 8;
    const int tn  = (t & 15) * 8;

    float acc[8][8];
#pragma unroll
    for (int i = 0; i < 8; i++)
#pragma unroll
        for (int j = 0; j < 8; j++) acc[i][j] = 0.0f;

    const int v0 = t * 2;  // two float4 loads per tile per operand

    for (int k0 = 0; k0 < DM; k0 += 16) {
#pragma unroll
        for (int jv = 0; jv < 2; ++jv) {
            int v   = v0 + jv;
            int row = v >> 2;
            int c4  = (v & 3) * 4;
            float4 a = *(const float4*)&A[(size_t)(bm0 + row) * DM + k0 + c4];
            As[c4 + 0][row] = a.x; As[c4 + 1][row] = a.y;
            As[c4 + 2][row] = a.z; As[c4 + 3][row] = a.w;
            float4 b = *(const float4*)&W[(size_t)(bn0 + row) * DM + k0 + c4];
            Bs[c4 + 0][row] = b.x; Bs[c4 + 1][row] = b.y;
            Bs[c4 + 2][row] = b.z; Bs[c4 + 3][row] = b.w;
        }
        __syncthreads();

#pragma unroll
        for (int kk = 0; kk < 16; kk++) {
            float4 a0 = *(const float4*)&As[kk][tm];
            float4 a1 = *(const float4*)&As[kk][tm + 4];
            float4 b0 = *(const float4*)&Bs[kk][tn];
            float4 b1 = *(const float4*)&Bs[kk][tn + 4];
            float ar[8] = {a0.x, a0.y, a0.z, a0.w, a1.x, a1.y, a1.z, a1.w};
            float br[8] = {b0.x, b0.y, b0.z, b0.w, b1.x, b1.y, b1.z, b1.w};
#pragma unroll
            for (int i = 0; i < 8; i++)
#pragma unroll
                for (int j = 0; j < 8; j++) acc[i][j] += ar[i] * br[j];
        }
        __syncthreads();
    }

    // epilogue
#pragma unroll
    for (int i = 0; i < 8; i++) {
        int gm = bm0 + tm + i;
#pragma unroll
        for (int j = 0; j < 8; j++) {
            int gn  = bn0 + tn + j;
            float v = acc[i][j];
            if (MODE == 0) {
                if (gn < DM) {
                    v += bias[gn];
                    float s = 1.0f / (1.0f + __expf(-v));
                    g_xconv[(size_t)gm * DM + gn] = v * s;
                } else {
                    g_z[(size_t)gm * HIDM + (gn - DM)] = v;
                }
            } else {
                out_primary[(size_t)gm * DM + gn] = v;
            }
        }
    }
}

// ---------------- gate kernel: one block per row, warp per head ----
__device__ __forceinline__ float softcap_f(float x) {
    return CAPV * tanhf(x * (1.0f / CAPV));
}

__global__ __launch_bounds__(256) void gates_kernel(
    const float* __restrict__ inp,
    const float* __restrict__ i_w, const float* __restrict__ i_b,
    const float* __restrict__ f_w, const float* __restrict__ f_b,
    const float* __restrict__ o_w, const float* __restrict__ o_b,
    const float* __restrict__ m_in, float* __restrict__ m_out) {
    __shared__ float s_xc[DM];
    __shared__ float s_in[DM];
    const int b = blockIdx.x;
    const int t = threadIdx.x;
    const float* xrow = &g_xconv[(size_t)b * DM];
    const float* irow = &inp[(size_t)b * DM];
    for (int k = t; k < DM; k += 256) {
        s_xc[k] = xrow[k];
        s_in[k] = irow[k];
    }
    __syncthreads();

    const int h = t >> 5;     // warp -> head (NHD==8 warps)
    const int lane = t & 31;
    const float* iw = &i_w[h * DM];
    const float* fw = &f_w[h * DM];
    const float* ow = &o_w[h * DM];

    float di = 0.f, df = 0.f, dz = 0.f;
#pragma unroll 4
    for (int k = lane; k < DM; k += 32) {
        float x = s_xc[k];
        di += x * iw[k];
        df += x * fw[k];
        dz += s_in[k] * ow[k];
    }
#pragma unroll
    for (int off = 16; off > 0; off >>= 1) {
        di += __shfl_down_sync(0xffffffffu, di, off);
        df += __shfl_down_sync(0xffffffffu, df, off);
        dz += __shfl_down_sync(0xffffffffu, dz, off);
    }
    if (lane == 0) {
        float it = softcap_f(di + i_b[h]);
        float ft = softcap_f(df + f_b[h]);
        float ot = softcap_f(dz + o_b[h]);
        float flog = -log1pf(expf(-ft));         // log(sigmoid(f_t))
        float mv   = m_in[b * NHD + h];
        float mn   = fmaxf(flog + mv, it);
        g_ig[b * NHD + h] = expf(it - mn);
        g_fg[b * NHD + h] = expf(flog + mv - mn);
        g_og[b * NHD + h] = 1.0f / (1.0f + expf(-ot));
        m_out[b * NHD + h] = mn;
    }
}

// ---------------- elementwise gating + per-head layernorm ----------
__global__ __launch_bounds__(128) void ewln_kernel(
    const float* __restrict__ c, const float* __restrict__ n,
    const float* __restrict__ gn_w, const float* __restrict__ gn_b,
    float* __restrict__ c_new, float* __restrict__ n_new) {
    const int bh = blockIdx.x;           // b*NHD + h
    const int h  = bh & (NHD - 1);
    const int e  = threadIdx.x;          // 0..127
    const size_t base = (size_t)bh * HD + e;

    const float ig = g_ig[bh];
    const float fg = g_fg[bh];
    const float og = g_og[bh];

    float cv = fg * c[base] + ig * g_z[base];
    float nv = fg * n[base] + ig;
    float hv = og * cv / (nv + EPSV);
    c_new[base] = cv;
    n_new[base] = nv;

    // block reduction of sum and sumsq over HD=128
    float s = hv, s2 = hv * hv;
#pragma unroll
    for (int off = 16; off > 0; off >>= 1) {
        s  += __shfl_down_sync(0xffffffffu, s, off);
        s2 += __shfl_down_sync(0xffffffffu, s2, off);
    }
    __shared__ float ws[4], ws2[4];
    const int w = e >> 5, lane = e & 31;
    if (lane == 0) { ws[w] = s; ws2[w] = s2; }
    __syncthreads();
    float st  = ws[0] + ws[1] + ws[2] + ws[3];
    float st2 = ws2[0] + ws2[1] + ws2[2] + ws2[3];
    float mu  = st * (1.0f / HD);
    float var = st2 * (1.0f / HD) - mu * mu;
    float hn  = (hv - mu) * rsqrtf(var + EPSV) * gn_w[h * HD + e] + gn_b[h * HD + e];
    g_hnorm[base] = hn;
}

// ---------------- launch ------------------------------------------
extern "C" void kernel_launch(void* const* d_in, const int* in_sizes, int n_in,
                              void* d_out, int out_size) {
    const float* inputs = (const float*)d_in[0];
    const float* c      = (const float*)d_in[1];
    const float* n      = (const float*)d_in[2];
    const float* m      = (const float*)d_in[3];
    const float* conv_w = (const float*)d_in[4];
    const float* conv_b = (const float*)d_in[5];
    const float* z_w    = (const float*)d_in[6];
    const float* i_w    = (const float*)d_in[7];
    const float* i_b    = (const float*)d_in[8];
    const float* f_w    = (const float*)d_in[9];
    const float* f_b    = (const float*)d_in[10];
    const float* o_w    = (const float*)d_in[11];
    const float* o_b    = (const float*)d_in[12];
    const float* gn_w   = (const float*)d_in[13];
    const float* gn_b   = (const float*)d_in[14];
    const float* out_w  = (const float*)d_in[15];

    float* out   = (float*)d_out;
    float* c_new = out + (size_t)BSZ * DM;
    float* n_new = c_new + (size_t)BSZ * NHD * HD;
    float* m_new = n_new + (size_t)BSZ * NHD * HD;

    // 1) pack conv last-tap + z weights into one [2048,1024] matrix
    pack_w_kernel<<<(2 * DM * DM + 255) / 256, 256>>>(conv_w, z_w);

    // 2) fused GEMM: x_conv (silu) and z
    gemm128_kernel<0><<<dim3(2 * DM / 128, BSZ / 128), 256>>>(inputs, nullptr, conv_b, nullptr);

    // 3) gates i/f/o + stabilized exp gate math -> m_new, ig/fg/og scratch
    gates_kernel<<<BSZ, 256>>>(inputs, i_w, i_b, f_w, f_b, o_w, o_b, m, m_new);

    // 4) elementwise cell update + per-head LN -> c_new, n_new, g_hnorm
    ewln_kernel<<<BSZ * NHD, 128>>>(c, n, gn_w, gn_b, c_new, n_new);

    // 5) out = h_norm @ out_w^T
    gemm128_kernel<1><<<dim3(DM / 128, BSZ / 128), 256>>>(nullptr, out_w, nullptr, out);
}

// round 5
// speedup vs baseline: 2.7657x; 2.7657x over previous
#include <cuda_runtime.h>
#include <cuda_bf16.h>
#include <math.h>
#include <stdint.h>

// ---------------- problem constants ----------------
#define BSZ 32768
#define DM  1024
#define NHD 8
#define HD  128
#define HIDM 1024
#define KSZ 4
#define EPSV 1e-6f
#define CAPV 15.0f

// ---------------- GEMM tiling ----------------
#define NCHUNK 48            // K_eff = 3072 = 48 chunks of 64 bf16
#define NS 4                 // pipeline stages
#define TM 128
#define TN 128
#define CHUNK_A 16384        // 128 rows x 128B (64 bf16)
#define CHUNK_B 16384        // 128 rows x 128B
#define STG (CHUNK_A + CHUNK_B)
#define SMEM_OFF 1024
#define SMEM_TOTAL (SMEM_OFF + NS * STG)

// ---------------- device scratch (no allocs) ----------------
__device__ __nv_bfloat16 g_Ahi[(size_t)BSZ * DM];
__device__ __nv_bfloat16 g_Alo[(size_t)BSZ * DM];
__device__ __nv_bfloat16 g_Hhi[(size_t)BSZ * HIDM];
__device__ __nv_bfloat16 g_Hlo[(size_t)BSZ * HIDM];
__device__ __nv_bfloat16 g_W1[(size_t)2048 * 3072];   // [ntile16][48][128x64 swz]
__device__ __nv_bfloat16 g_W2[(size_t)1024 * 3072];   // [ntile8][48][128x64 swz]
__device__ float g_xconv[(size_t)BSZ * DM];
__device__ float g_z[(size_t)BSZ * HIDM];
__device__ float g_ig[BSZ * NHD];
__device__ float g_fg[BSZ * NHD];
__device__ float g_og[BSZ * NHD];

// ---------------- PTX helpers (all non-'a' features) ----------------
__device__ __forceinline__ uint32_t swz128(uint32_t off) { return off ^ ((off >> 3) & 0x70); }

__device__ __forceinline__ uint32_t s2u(const void* p) {
    uint32_t a;
    asm("{ .reg .u64 t; cvta.to.shared.u64 t, %1; cvt.u32.u64 %0, t; }" : "=r"(a) : "l"(p));
    return a;
}
__device__ __forceinline__ void mbar_init(uint32_t mbar, uint32_t cnt) {
    asm volatile("mbarrier.init.shared.b64 [%0], %1;" :: "r"(mbar), "r"(cnt) : "memory");
}
__device__ __forceinline__ void mbar_expect(uint32_t mbar, uint32_t bytes) {
    asm volatile("mbarrier.arrive.expect_tx.shared.b64 _, [%0], %1;" :: "r"(mbar), "r"(bytes) : "memory");
}
__device__ __forceinline__ void mbar_arrive(uint32_t mbar) {
    asm volatile("mbarrier.arrive.shared.b64 _, [%0];" :: "r"(mbar) : "memory");
}
__device__ __forceinline__ void mbar_wait(uint32_t mbar, uint32_t parity) {
    uint32_t done;
    asm volatile("{\n\t.reg .pred p;\n\t"
        "mbarrier.try_wait.parity.acquire.cta.shared::cta.b64 p, [%1], %2;\n\t"
        "selp.b32 %0, 1, 0, p;\n\t}"
        : "=r"(done) : "r"(mbar), "r"(parity) : "memory");
    while (!done) {
        asm volatile("{\n\t.reg .pred p;\n\t"
            "mbarrier.try_wait.parity.acquire.cta.shared::cta.b64 p, [%1], %2, 0x989680;\n\t"
            "selp.b32 %0, 1, 0, p;\n\t}"
            : "=r"(done) : "r"(mbar), "r"(parity) : "memory");
    }
}
__device__ __forceinline__ void bulk_g2s(uint32_t dst, const void* src, uint32_t bytes, uint32_t mbar) {
    asm volatile("cp.async.bulk.shared::cluster.global.mbarrier::complete_tx::bytes [%0], [%1], %2, [%3];"
        :: "r"(dst), "l"(src), "r"(bytes), "r"(mbar) : "memory");
}
__device__ __forceinline__ void ldmx4(uint32_t* r, uint32_t addr) {
    asm volatile("ldmatrix.sync.aligned.m8n8.x4.shared.b16 {%0,%1,%2,%3}, [%4];"
        : "=r"(r[0]), "=r"(r[1]), "=r"(r[2]), "=r"(r[3]) : "r"(addr));
}
__device__ __forceinline__ void mma16816(float* d, const uint32_t* a, uint32_t b0, uint32_t b1) {
    asm volatile("mma.sync.aligned.m16n8k16.row.col.f32.bf16.bf16.f32 "
        "{%0,%1,%2,%3}, {%4,%5,%6,%7}, {%8,%9}, {%0,%1,%2,%3};"
        : "+f"(d[0]), "+f"(d[1]), "+f"(d[2]), "+f"(d[3])
        : "r"(a[0]), "r"(a[1]), "r"(a[2]), "r"(a[3]), "r"(b0), "r"(b1));
}

// ---------------- weight packing: W1=[conv_tap|z_w], W2=out_w ----------------
// Per N-tile of 128 rows: 48 chunks of [128 x 64 bf16] swizzled; K-layout
// segments: [0:16)=hi vs A_hi, [16:32)=hi vs A_lo, [32:48)=lo vs A_hi.
__global__ __launch_bounds__(256) void pack_w_kernel(const float* __restrict__ conv_w,
                                                     const float* __restrict__ z_w,
                                                     const float* __restrict__ out_w) {
    int idx = blockIdx.x * 256 + threadIdx.x;
    if (idx >= 3072 * 512) return;
    int n = idx >> 9;
    int k = (idx & 511) << 1;
    float v0, v1;
    if (n < 1024) {
        v0 = conv_w[((size_t)n * DM + k) * KSZ + (KSZ - 1)];
        v1 = conv_w[((size_t)n * DM + k + 1) * KSZ + (KSZ - 1)];
    } else if (n < 2048) {
        const float* p = &z_w[(size_t)(n - 1024) * DM + k];
        v0 = p[0]; v1 = p[1];
    } else {
        const float* p = &out_w[(size_t)(n - 2048) * DM + k];
        v0 = p[0]; v1 = p[1];
    }
    __nv_bfloat16 h0 = __float2bfloat16(v0), h1 = __float2bfloat16(v1);
    __nv_bfloat16 l0 = __float2bfloat16(v0 - __bfloat162float(h0));
    __nv_bfloat16 l1 = __float2bfloat16(v1 - __bfloat162float(h1));
    __nv_bfloat162 hp; hp.x = h0; hp.y = h1;
    __nv_bfloat162 lp; lp.x = l0; lp.y = l1;

    char* base; int nl;
    if (n < 2048) { base = (char*)g_W1; nl = n; }
    else          { base = (char*)g_W2; nl = n - 2048; }
    int ntile = nl >> 7, nr = nl & 127;
    int kc = k >> 6;
    uint32_t inoff = swz128((uint32_t)nr * 128 + (uint32_t)(k & 63) * 2);
    size_t b0 = ((size_t)(ntile * NCHUNK + kc)) * CHUNK_B + inoff;
    size_t b1 = ((size_t)(ntile * NCHUNK + 16 + kc)) * CHUNK_B + inoff;
    size_t b2 = ((size_t)(ntile * NCHUNK + 32 + kc)) * CHUNK_B + inoff;
    *(__nv_bfloat162*)(base + b0) = hp;
    *(__nv_bfloat162*)(base + b1) = hp;
    *(__nv_bfloat162*)(base + b2) = lp;
}

// ---------------- inputs -> blocked swizzled bf16 hi/lo ----------------
__global__ __launch_bounds__(256) void conv_in_kernel(const float* __restrict__ inp) {
    int idx = blockIdx.x * 256 + threadIdx.x;
    int b = idx >> 9;
    int k = (idx & 511) << 1;
    float2 v = *(const float2*)&inp[(size_t)b * DM + k];
    __nv_bfloat16 h0 = __float2bfloat16(v.x), h1 = __float2bfloat16(v.y);
    __nv_bfloat16 l0 = __float2bfloat16(v.x - __bfloat162float(h0));
    __nv_bfloat16 l1 = __float2bfloat16(v.y - __bfloat162float(h1));
    __nv_bfloat162 hp; hp.x = h0; hp.y = h1;
    __nv_bfloat162 lp; lp.x = l0; lp.y = l1;
    int mtile = b >> 7, r = b & 127, kc = k >> 6;
    size_t off = ((size_t)(mtile * 16 + kc)) * CHUNK_A + swz128((uint32_t)r * 128 + (uint32_t)(k & 63) * 2);
    *(__nv_bfloat162*)((char*)g_Ahi + off) = hp;
    *(__nv_bfloat162*)((char*)g_Alo + off) = lp;
}

// ---------------- HMMA GEMM, tile 128x128, K_eff=3072 (3-seg bf16 split) ----
// 9 warps: warp 8 = bulk-copy producer, warps 0-7 = 64x32 compute tiles.
// MODE 0: W=g_W1 (N=2048): ntile<8 -> silu(+bias) -> g_xconv, else -> g_z.
// MODE 1: W=g_W2 (N=1024): plain store -> out.
template <int MODE>
__global__ __launch_bounds__(288) void hmma_gemm_kernel(const float* __restrict__ bias,
                                                        float* __restrict__ outp) {
    extern __shared__ __align__(1024) char smem[];
    uint32_t sb = s2u(smem);
    const int tid = threadIdx.x, wid = tid >> 5, lane = tid & 31;
    const int mtile = blockIdx.y, ntile = blockIdx.x;

    if (tid == 0) {
        for (int s = 0; s < NS; s++) {
            mbar_init(sb + s * 8, 1);          // full (tx-based)
            mbar_init(sb + 64 + s * 8, 8);     // empty (8 consumer warps)
        }
        asm volatile("fence.proxy.async.shared::cta;" ::: "memory");
    }
    __syncthreads();

    if (wid == 8) {
        // ---------------- producer ----------------
        if (lane == 0) {
            const __nv_bfloat16* Ahi = MODE ? g_Hhi : g_Ahi;
            const __nv_bfloat16* Alo = MODE ? g_Hlo : g_Alo;
            const __nv_bfloat16* W   = MODE ? g_W2  : g_W1;
            for (int c = 0; c < NCHUNK; c++) {
                int s = c & (NS - 1);
                mbar_wait(sb + 64 + s * 8, 1u ^ ((c >> 2) & 1));
                uint32_t full = sb + s * 8;
                mbar_expect(full, STG);
                int seg = c >> 4, kk = c & 15;
                const char* ab = (const char*)((seg == 1) ? Alo : Ahi) +
                                 ((size_t)(mtile * 16 + kk)) * CHUNK_A;
                const char* bb = (const char*)W + ((size_t)(ntile * NCHUNK + c)) * CHUNK_B;
                uint32_t da = sb + SMEM_OFF + s * STG;
                bulk_g2s(da, ab, CHUNK_A, full);
                bulk_g2s(da + CHUNK_A, bb, CHUNK_B, full);
            }
        }
        return;
    }

    // ---------------- consumers: warp (wm, wn) computes 64x32 ----------------
    const int wm = wid >> 2, wn = wid & 3;
    const int m0 = wm * 64, n0 = wn * 32;
    const int li = lane & 7, lg = lane >> 3;

    float d[16][4];
#pragma unroll
    for (int i = 0; i < 16; i++)
#pragma unroll
        for (int j = 0; j < 4; j++) d[i][j] = 0.0f;

    // per-lane ldmatrix row offsets (bytes) and swizzle xor
    uint32_t aoff[4], boff[2];
#pragma unroll
    for (int mt = 0; mt < 4; mt++)
        aoff[mt] = (uint32_t)(m0 + mt * 16 + 8 * (lg & 1) + li) * 128;
#pragma unroll
    for (int bt = 0; bt < 2; bt++)
        boff[bt] = (uint32_t)(n0 + bt * 16 + 8 * (lg >> 1) + li) * 128;
    const uint32_t acb = (uint32_t)(lg >> 1) * 16;   // A k-half select
    const uint32_t bcb = (uint32_t)(lg & 1) * 16;    // B k-half select
    const uint32_t sw  = (uint32_t)li * 16;          // swizzle xor (row&7)*16

    for (int c = 0; c < NCHUNK; c++) {
        int s = c & (NS - 1);
        mbar_wait(sb + s * 8, (c >> 2) & 1);
        uint32_t ab = sb + SMEM_OFF + s * STG;
        uint32_t bb = ab + CHUNK_A;
#pragma unroll
        for (int ks = 0; ks < 4; ks++) {
            uint32_t k2 = (uint32_t)ks * 32;
            uint32_t a[4][4], bf[2][4];
#pragma unroll
            for (int mt = 0; mt < 4; mt++)
                ldmx4(a[mt], ab + aoff[mt] + ((k2 + acb) ^ sw));
#pragma unroll
            for (int bt = 0; bt < 2; bt++)
                ldmx4(bf[bt], bb + boff[bt] + ((k2 + bcb) ^ sw));
#pragma unroll
            for (int mt = 0; mt < 4; mt++)
#pragma unroll
                for (int nt = 0; nt < 4; nt++)
                    mma16816(d[mt * 4 + nt], a[mt],
                             bf[nt >> 1][(nt & 1) * 2], bf[nt >> 1][(nt & 1) * 2 + 1]);
        }
        if (lane == 0) mbar_arrive(sb + 64 + s * 8);
    }

    // ---------------- epilogue ----------------
    const int mrow = mtile * TM + m0 + (lane >> 2);
    const int gnb  = ntile * TN + n0 + (lane & 3) * 2;
#pragma unroll
    for (int mt = 0; mt < 4; mt++) {
#pragma unroll
        for (int nt = 0; nt < 4; nt++) {
            const float* dd = d[mt * 4 + nt];
            int gm = mrow + mt * 16;
            int gn = gnb + nt * 8;
            if (MODE == 0) {
                if (ntile < 8) {
                    float a0 = dd[0] + bias[gn], a1 = dd[1] + bias[gn + 1];
                    float a2 = dd[2] + bias[gn], a3 = dd[3] + bias[gn + 1];
                    float2 lo, hi;
                    lo.x = a0 / (1.0f + __expf(-a0)); lo.y = a1 / (1.0f + __expf(-a1));
                    hi.x = a2 / (1.0f + __expf(-a2)); hi.y = a3 / (1.0f + __expf(-a3));
                    *(float2*)&g_xconv[(size_t)gm * DM + gn] = lo;
                    *(float2*)&g_xconv[(size_t)(gm + 8) * DM + gn] = hi;
                } else {
                    float2 lo = {dd[0], dd[1]}, hi = {dd[2], dd[3]};
                    int zc = gn - DM;
                    *(float2*)&g_z[(size_t)gm * HIDM + zc] = lo;
                    *(float2*)&g_z[(size_t)(gm + 8) * HIDM + zc] = hi;
                }
            } else {
                float2 lo = {dd[0], dd[1]}, hi = {dd[2], dd[3]};
                *(float2*)&outp[(size_t)gm * DM + gn] = lo;
                *(float2*)&outp[(size_t)(gm + 8) * DM + gn] = hi;
            }
        }
    }
}

// ---------------- gate kernel ----------------
__device__ __forceinline__ float softcap_f(float x) {
    return CAPV * tanhf(x * (1.0f / CAPV));
}

__global__ __launch_bounds__(256) void gates_kernel(
    const float* __restrict__ inp,
    const float* __restrict__ i_w, const float* __restrict__ i_b,
    const float* __restrict__ f_w, const float* __restrict__ f_b,
    const float* __restrict__ o_w, const float* __restrict__ o_b,
    const float* __restrict__ m_in, float* __restrict__ m_out) {
    __shared__ float s_xc[DM];
    __shared__ float s_in[DM];
    const int b = blockIdx.x;
    const int t = threadIdx.x;
    const float* xrow = &g_xconv[(size_t)b * DM];
    const float* irow = &inp[(size_t)b * DM];
    for (int k = t; k < DM; k += 256) {
        s_xc[k] = xrow[k];
        s_in[k] = irow[k];
    }
    __syncthreads();

    const int h = t >> 5;
    const int lane = t & 31;
    const float* iw = &i_w[h * DM];
    const float* fw = &f_w[h * DM];
    const float* ow = &o_w[h * DM];

    float di = 0.f, df = 0.f, dz = 0.f;
#pragma unroll 4
    for (int k = lane; k < DM; k += 32) {
        float x = s_xc[k];
        di += x * iw[k];
        df += x * fw[k];
        dz += s_in[k] * ow[k];
    }
#pragma unroll
    for (int off = 16; off > 0; off >>= 1) {
        di += __shfl_down_sync(0xffffffffu, di, off);
        df += __shfl_down_sync(0xffffffffu, df, off);
        dz += __shfl_down_sync(0xffffffffu, dz, off);
    }
    if (lane == 0) {
        float it = softcap_f(di + i_b[h]);
        float ft = softcap_f(df + f_b[h]);
        float ot = softcap_f(dz + o_b[h]);
        float flog = -log1pf(expf(-ft));
        float mv   = m_in[b * NHD + h];
        float mn   = fmaxf(flog + mv, it);
        g_ig[b * NHD + h] = expf(it - mn);
        g_fg[b * NHD + h] = expf(flog + mv - mn);
        g_og[b * NHD + h] = 1.0f / (1.0f + expf(-ot));
        m_out[b * NHD + h] = mn;
    }
}

// ---------------- elementwise + per-head LN; emits blocked bf16 hi/lo ------
__global__ __launch_bounds__(128) void ewln_kernel(
    const float* __restrict__ c, const float* __restrict__ n,
    const float* __restrict__ gn_w, const float* __restrict__ gn_b,
    float* __restrict__ c_new, float* __restrict__ n_new) {
    const int bh = blockIdx.x;
    const int h  = bh & (NHD - 1);
    const int e  = threadIdx.x;
    const size_t base = (size_t)bh * HD + e;

    const float ig = g_ig[bh];
    const float fg = g_fg[bh];
    const float og = g_og[bh];

    float cv = fg * c[base] + ig * g_z[base];
    float nv = fg * n[base] + ig;
    float hv = og * cv / (nv + EPSV);
    c_new[base] = cv;
    n_new[base] = nv;

    float s = hv, s2 = hv * hv;
#pragma unroll
    for (int off = 16; off > 0; off >>= 1) {
        s  += __shfl_down_sync(0xffffffffu, s, off);
        s2 += __shfl_down_sync(0xffffffffu, s2, off);
    }
    __shared__ float ws[4], ws2[4];
    const int w = e >> 5, lane = e & 31;
    if (lane == 0) { ws[w] = s; ws2[w] = s2; }
    __syncthreads();
    float st  = ws[0] + ws[1] + ws[2] + ws[3];
    float st2 = ws2[0] + ws2[1] + ws2[2] + ws2[3];
    float mu  = st * (1.0f / HD);
    float var = st2 * (1.0f / HD) - mu * mu;
    float hn  = (hv - mu) * rsqrtf(var + EPSV) * gn_w[h * HD + e] + gn_b[h * HD + e];

    float pn = __shfl_xor_sync(0xffffffffu, hn, 1);
    if (!(e & 1)) {
        __nv_bfloat16 h0 = __float2bfloat16(hn), h1 = __float2bfloat16(pn);
        __nv_bfloat16 l0 = __float2bfloat16(hn - __bfloat162float(h0));
        __nv_bfloat16 l1 = __float2bfloat16(pn - __bfloat162float(h1));
        __nv_bfloat162 hp; hp.x = h0; hp.y = h1;
        __nv_bfloat162 lp; lp.x = l0; lp.y = l1;
        int b = bh >> 3;
        int col = h * HD + e;
        int mtile = b >> 7, r = b & 127, kc = col >> 6;
        size_t off = ((size_t)(mtile * 16 + kc)) * CHUNK_A +
                     swz128((uint32_t)r * 128 + (uint32_t)(col & 63) * 2);
        *(__nv_bfloat162*)((char*)g_Hhi + off) = hp;
        *(__nv_bfloat162*)((char*)g_Hlo + off) = lp;
    }
}

// ---------------- launch ------------------------------------------
extern "C" void kernel_launch(void* const* d_in, const int* in_sizes, int n_in,
                              void* d_out, int out_size) {
    const float* inputs = (const float*)d_in[0];
    const float* c      = (const float*)d_in[1];
    const float* n      = (const float*)d_in[2];
    const float* m      = (const float*)d_in[3];
    const float* conv_w = (const float*)d_in[4];
    const float* conv_b = (const float*)d_in[5];
    const float* z_w    = (const float*)d_in[6];
    const float* i_w    = (const float*)d_in[7];
    const float* i_b    = (const float*)d_in[8];
    const float* f_w    = (const float*)d_in[9];
    const float* f_b    = (const float*)d_in[10];
    const float* o_w    = (const float*)d_in[11];
    const float* o_b    = (const float*)d_in[12];
    const float* gn_w   = (const float*)d_in[13];
    const float* gn_b   = (const float*)d_in[14];
    const float* out_w  = (const float*)d_in[15];

    float* out   = (float*)d_out;
    float* c_new = out + (size_t)BSZ * DM;
    float* n_new = c_new + (size_t)BSZ * NHD * HD;
    float* m_new = n_new + (size_t)BSZ * NHD * HD;

    cudaFuncSetAttribute(hmma_gemm_kernel<0>, cudaFuncAttributeMaxDynamicSharedMemorySize, SMEM_TOTAL);
    cudaFuncSetAttribute(hmma_gemm_kernel<1>, cudaFuncAttributeMaxDynamicSharedMemorySize, SMEM_TOTAL);

    // 1) pack weights (hi/hi/lo K-duplicated, blocked+swizzled)
    pack_w_kernel<<<(3072 * 512 + 255) / 256, 256>>>(conv_w, z_w, out_w);

    // 2) convert inputs to blocked bf16 hi/lo
    conv_in_kernel<<<(BSZ * 512 + 255) / 256, 256>>>(inputs);

    // 3) GEMM1: [xconv | z]
    hmma_gemm_kernel<0><<<dim3(16, BSZ / TM), 288, SMEM_TOTAL>>>(conv_b, nullptr);

    // 4) gates
    gates_kernel<<<BSZ, 256>>>(inputs, i_w, i_b, f_w, f_b, o_w, o_b, m, m_new);

    // 5) elementwise + LN (emits h_norm bf16 hi/lo blocked)
    ewln_kernel<<<BSZ * NHD, 128>>>(c, n, gn_w, gn_b, c_new, n_new);

    // 6) GEMM2: out = h_norm @ out_w^T
    hmma_gemm_kernel<1><<<dim3(8, BSZ / TM), 288, SMEM_TOTAL>>>(nullptr, out);
}

// round 7
// speedup vs baseline: 2.9013x; 1.0490x over previous
#include <cuda_runtime.h>
#include <cuda_bf16.h>
#include <math.h>
#include <stdint.h>

// ---------------- problem constants ----------------
#define BSZ 32768
#define DM  1024
#define NHD 8
#define HD  128
#define HIDM 1024
#define KSZ 4
#define EPSV 1e-6f
#define CAPV 15.0f

// ---------------- GEMM tiling ----------------
#define NCHUNK 48            // K_eff = 3072 = 48 chunks of 64 bf16
#define NS 4                 // pipeline stages
#define TM 128
#define TN 256
#define CHUNK_A 16384        // 128 rows x 128B (64 bf16)
#define CHUNK_B 32768        // 256 rows x 128B
#define STG (CHUNK_A + CHUNK_B)
#define SMEM_OFF 1024
#define SMEM_TOTAL (SMEM_OFF + NS * STG)

// ---------------- device scratch (no allocs) ----------------
__device__ __nv_bfloat16 g_Ahi[(size_t)BSZ * DM];
__device__ __nv_bfloat16 g_Alo[(size_t)BSZ * DM];
__device__ __nv_bfloat16 g_Hhi[(size_t)BSZ * HIDM];
__device__ __nv_bfloat16 g_Hlo[(size_t)BSZ * HIDM];
__device__ __nv_bfloat16 g_W1[(size_t)2048 * 3072];   // [ntile8(256)][48][256x64 swz]
__device__ __nv_bfloat16 g_W2[(size_t)1024 * 3072];   // [ntile4(256)][48][256x64 swz]
__device__ float g_xconv[(size_t)BSZ * DM];
__device__ float g_z[(size_t)BSZ * HIDM];

// ---------------- PTX helpers (all non-'a' features) ----------------
__device__ __forceinline__ uint32_t swz128(uint32_t off) { return off ^ ((off >> 3) & 0x70); }

__device__ __forceinline__ uint32_t s2u(const void* p) {
    uint32_t a;
    asm("{ .reg .u64 t; cvta.to.shared.u64 t, %1; cvt.u32.u64 %0, t; }" : "=r"(a) : "l"(p));
    return a;
}
__device__ __forceinline__ void mbar_init(uint32_t mbar, uint32_t cnt) {
    asm volatile("mbarrier.init.shared.b64 [%0], %1;" :: "r"(mbar), "r"(cnt) : "memory");
}
__device__ __forceinline__ void mbar_expect(uint32_t mbar, uint32_t bytes) {
    asm volatile("mbarrier.arrive.expect_tx.shared.b64 _, [%0], %1;" :: "r"(mbar), "r"(bytes) : "memory");
}
__device__ __forceinline__ void mbar_arrive(uint32_t mbar) {
    asm volatile("mbarrier.arrive.shared.b64 _, [%0];" :: "r"(mbar) : "memory");
}
__device__ __forceinline__ void mbar_wait(uint32_t mbar, uint32_t parity) {
    uint32_t done;
    asm volatile("{\n\t.reg .pred p;\n\t"
        "mbarrier.try_wait.parity.acquire.cta.shared::cta.b64 p, [%1], %2;\n\t"
        "selp.b32 %0, 1, 0, p;\n\t}"
        : "=r"(done) : "r"(mbar), "r"(parity) : "memory");
    while (!done) {
        asm volatile("{\n\t.reg .pred p;\n\t"
            "mbarrier.try_wait.parity.acquire.cta.shared::cta.b64 p, [%1], %2, 0x989680;\n\t"
            "selp.b32 %0, 1, 0, p;\n\t}"
            : "=r"(done) : "r"(mbar), "r"(parity) : "memory");
    }
}
__device__ __forceinline__ void bulk_g2s(uint32_t dst, const void* src, uint32_t bytes, uint32_t mbar) {
    asm volatile("cp.async.bulk.shared::cluster.global.mbarrier::complete_tx::bytes [%0], [%1], %2, [%3];"
        :: "r"(dst), "l"(src), "r"(bytes), "r"(mbar) : "memory");
}
__device__ __forceinline__ void ldmx4(uint32_t* r, uint32_t addr) {
    asm volatile("ldmatrix.sync.aligned.m8n8.x4.shared.b16 {%0,%1,%2,%3}, [%4];"
        : "=r"(r[0]), "=r"(r[1]), "=r"(r[2]), "=r"(r[3]) : "r"(addr));
}
__device__ __forceinline__ void mma16816(float* d, const uint32_t* a, uint32_t b0, uint32_t b1) {
    asm volatile("mma.sync.aligned.m16n8k16.row.col.f32.bf16.bf16.f32 "
        "{%0,%1,%2,%3}, {%4,%5,%6,%7}, {%8,%9}, {%0,%1,%2,%3};"
        : "+f"(d[0]), "+f"(d[1]), "+f"(d[2]), "+f"(d[3])
        : "r"(a[0]), "r"(a[1]), "r"(a[2]), "r"(a[3]), "r"(b0), "r"(b1));
}

// ---------------- weight packing: W1=[conv_tap|z_w], W2=out_w ----------------
// Per N-tile of 256 rows: 48 chunks of [256 x 64 bf16] swizzled; segments:
// [0:16)=hi (vs A_hi), [16:32)=hi (vs A_lo), [32:48)=lo (vs A_hi).
__global__ __launch_bounds__(256) void pack_w_kernel(const float* __restrict__ conv_w,
                                                     const float* __restrict__ z_w,
                                                     const float* __restrict__ out_w) {
    int idx = blockIdx.x * 256 + threadIdx.x;
    if (idx >= 3072 * 512) return;
    int n = idx >> 9;
    int k = (idx & 511) << 1;
    float v0, v1;
    if (n < 1024) {
        v0 = conv_w[((size_t)n * DM + k) * KSZ + (KSZ - 1)];
        v1 = conv_w[((size_t)n * DM + k + 1) * KSZ + (KSZ - 1)];
    } else if (n < 2048) {
        const float* p = &z_w[(size_t)(n - 1024) * DM + k];
        v0 = p[0]; v1 = p[1];
    } else {
        const float* p = &out_w[(size_t)(n - 2048) * DM + k];
        v0 = p[0]; v1 = p[1];
    }
    __nv_bfloat16 h0 = __float2bfloat16(v0), h1 = __float2bfloat16(v1);
    __nv_bfloat16 l0 = __float2bfloat16(v0 - __bfloat162float(h0));
    __nv_bfloat16 l1 = __float2bfloat16(v1 - __bfloat162float(h1));
    __nv_bfloat162 hp; hp.x = h0; hp.y = h1;
    __nv_bfloat162 lp; lp.x = l0; lp.y = l1;

    char* base; int nl;
    if (n < 2048) { base = (char*)g_W1; nl = n; }
    else          { base = (char*)g_W2; nl = n - 2048; }
    int ntile = nl >> 8, nr = nl & 255;
    int kc = k >> 6;
    uint32_t inoff = swz128((uint32_t)nr * 128 + (uint32_t)(k & 63) * 2);
    size_t b0 = ((size_t)(ntile * NCHUNK + kc)) * CHUNK_B + inoff;
    size_t b1 = ((size_t)(ntile * NCHUNK + 16 + kc)) * CHUNK_B + inoff;
    size_t b2 = ((size_t)(ntile * NCHUNK + 32 + kc)) * CHUNK_B + inoff;
    *(__nv_bfloat162*)(base + b0) = hp;
    *(__nv_bfloat162*)(base + b1) = hp;
    *(__nv_bfloat162*)(base + b2) = lp;
}

// ---------------- inputs -> blocked swizzled bf16 hi/lo (float4) ----------------
__global__ __launch_bounds__(256) void conv_in_kernel(const float* __restrict__ inp) {
    int idx = blockIdx.x * 256 + threadIdx.x;   // BSZ*256 threads
    int b = idx >> 8;
    int k = (idx & 255) << 2;
    float4 v = *(const float4*)&inp[(size_t)b * DM + k];
    __nv_bfloat16 h0 = __float2bfloat16(v.x), h1 = __float2bfloat16(v.y);
    __nv_bfloat16 h2 = __float2bfloat16(v.z), h3 = __float2bfloat16(v.w);
    __nv_bfloat162 hp0; hp0.x = h0; hp0.y = h1;
    __nv_bfloat162 hp1; hp1.x = h2; hp1.y = h3;
    __nv_bfloat162 lp0, lp1;
    lp0.x = __float2bfloat16(v.x - __bfloat162float(h0));
    lp0.y = __float2bfloat16(v.y - __bfloat162float(h1));
    lp1.x = __float2bfloat16(v.z - __bfloat162float(h2));
    lp1.y = __float2bfloat16(v.w - __bfloat162float(h3));
    uint2 hu, lu;
    hu.x = *(uint32_t*)&hp0; hu.y = *(uint32_t*)&hp1;
    lu.x = *(uint32_t*)&lp0; lu.y = *(uint32_t*)&lp1;
    int mtile = b >> 7, r = b & 127, kc = k >> 6;
    size_t off = ((size_t)(mtile * 16 + kc)) * CHUNK_A + swz128((uint32_t)r * 128 + (uint32_t)(k & 63) * 2);
    *(uint2*)((char*)g_Ahi + off) = hu;
    *(uint2*)((char*)g_Alo + off) = lu;
}

// ---------------- HMMA GEMM, tile 128x256, K_eff=3072 ----------------
// 9 warps: warp 8 = bulk-copy producer, warps 0-7 = 64x64 compute tiles (2x4).
// MODE 0: W=g_W1 (N=2048): ntile<4 -> silu(+bias) -> g_xconv, else -> g_z.
// MODE 1: W=g_W2 (N=1024): plain store -> out.
template <int MODE>
__global__ __launch_bounds__(288, 1) void hmma_gemm_kernel(const float* __restrict__ bias,
                                                           float* __restrict__ outp) {
    extern __shared__ __align__(1024) char smem[];
    uint32_t sb = s2u(smem);
    const int tid = threadIdx.x, wid = tid >> 5, lane = tid & 31;
    const int mtile = blockIdx.y, ntile = blockIdx.x;

    if (tid == 0) {
        for (int s = 0; s < NS; s++) {
            mbar_init(sb + s * 8, 1);          // full (tx-based)
            mbar_init(sb + 64 + s * 8, 8);     // empty (8 consumer warps)
        }
        asm volatile("fence.proxy.async.shared::cta;" ::: "memory");
    }
    __syncthreads();

    if (wid == 8) {
        if (lane == 0) {
            const __nv_bfloat16* Ahi = MODE ? g_Hhi : g_Ahi;
            const __nv_bfloat16* Alo = MODE ? g_Hlo : g_Alo;
            const __nv_bfloat16* W   = MODE ? g_W2  : g_W1;
            for (int c = 0; c < NCHUNK; c++) {
                int s = c & (NS - 1);
                mbar_wait(sb + 64 + s * 8, 1u ^ ((c >> 2) & 1));
                uint32_t full = sb + s * 8;
                mbar_expect(full, STG);
                int seg = c >> 4, kk = c & 15;
                const char* ab = (const char*)((seg == 1) ? Alo : Ahi) +
                                 ((size_t)(mtile * 16 + kk)) * CHUNK_A;
                const char* bb = (const char*)W + ((size_t)(ntile * NCHUNK + c)) * CHUNK_B;
                uint32_t da = sb + SMEM_OFF + s * STG;
                bulk_g2s(da, ab, CHUNK_A, full);
                bulk_g2s(da + CHUNK_A, bb, CHUNK_B, full);
            }
        }
        return;
    }

    // consumers: warp (wm, wn) computes 64x64
    const int wm = wid >> 2, wn = wid & 3;
    const int m0 = wm * 64, n0 = wn * 64;
    const int li = lane & 7, lg = lane >> 3;

    float d[32][4];
#pragma unroll
    for (int i = 0; i < 32; i++)
#pragma unroll
        for (int j = 0; j < 4; j++) d[i][j] = 0.0f;

    uint32_t aoff[4], boff[4];
#pragma unroll
    for (int mt = 0; mt < 4; mt++)
        aoff[mt] = (uint32_t)(m0 + mt * 16 + 8 * (lg & 1) + li) * 128;
#pragma unroll
    for (int bt = 0; bt < 4; bt++)
        boff[bt] = (uint32_t)(n0 + bt * 16 + 8 * (lg >> 1) + li) * 128;
    const uint32_t acb = (uint32_t)(lg >> 1) * 16;
    const uint32_t bcb = (uint32_t)(lg & 1) * 16;
    const uint32_t sw  = (uint32_t)li * 16;

    for (int c = 0; c < NCHUNK; c++) {
        int s = c & (NS - 1);
        mbar_wait(sb + s * 8, (c >> 2) & 1);
        uint32_t ab = sb + SMEM_OFF + s * STG;
        uint32_t bb = ab + CHUNK_A;
#pragma unroll
        for (int ks = 0; ks < 4; ks++) {
            uint32_t k2 = (uint32_t)ks * 32;
            uint32_t a[4][4], bf[4][4];
#pragma unroll
            for (int mt = 0; mt < 4; mt++)
                ldmx4(a[mt], ab + aoff[mt] + ((k2 + acb) ^ sw));
#pragma unroll
            for (int bt = 0; bt < 4; bt++)
                ldmx4(bf[bt], bb + boff[bt] + ((k2 + bcb) ^ sw));
#pragma unroll
            for (int mt = 0; mt < 4; mt++)
#pragma unroll
                for (int nt = 0; nt < 8; nt++)
                    mma16816(d[mt * 8 + nt], a[mt],
                             bf[nt >> 1][(nt & 1) * 2], bf[nt >> 1][(nt & 1) * 2 + 1]);
        }
        if (lane == 0) mbar_arrive(sb + 64 + s * 8);
    }

    // epilogue
    const int mrow = mtile * TM + m0 + (lane >> 2);
    const int gnb  = ntile * TN + n0 + (lane & 3) * 2;
#pragma unroll
    for (int mt = 0; mt < 4; mt++) {
#pragma unroll
        for (int nt = 0; nt < 8; nt++) {
            const float* dd = d[mt * 8 + nt];
            int gm = mrow + mt * 16;
            int gn = gnb + nt * 8;
            if (MODE == 0) {
                if (ntile < 4) {
                    float a0 = dd[0] + bias[gn], a1 = dd[1] + bias[gn + 1];
                    float a2 = dd[2] + bias[gn], a3 = dd[3] + bias[gn + 1];
                    float2 lo, hi;
                    lo.x = a0 / (1.0f + __expf(-a0)); lo.y = a1 / (1.0f + __expf(-a1));
                    hi.x = a2 / (1.0f + __expf(-a2)); hi.y = a3 / (1.0f + __expf(-a3));
                    *(float2*)&g_xconv[(size_t)gm * DM + gn] = lo;
                    *(float2*)&g_xconv[(size_t)(gm + 8) * DM + gn] = hi;
                } else {
                    float2 lo = {dd[0], dd[1]}, hi = {dd[2], dd[3]};
                    int zc = gn - DM;
                    *(float2*)&g_z[(size_t)gm * HIDM + zc] = lo;
                    *(float2*)&g_z[(size_t)(gm + 8) * HIDM + zc] = hi;
                }
            } else {
                float2 lo = {dd[0], dd[1]}, hi = {dd[2], dd[3]};
                *(float2*)&outp[(size_t)gm * DM + gn] = lo;
                *(float2*)&outp[(size_t)(gm + 8) * DM + gn] = hi;
            }
        }
    }
}

// ---------------- fused gates + elementwise + per-head LN ----------------
// One block (256 thr) per batch row. Phase 1: 8 warps compute i/f/o dots
// (float4 loads). Phase 2: warp h handles head h (4 elems/lane, float4).
__device__ __forceinline__ float softcap_f(float x) {
    return CAPV * tanhf(x * (1.0f / CAPV));
}

__global__ __launch_bounds__(256) void gact_kernel(
    const float* __restrict__ inp,
    const float* __restrict__ i_w, const float* __restrict__ i_b,
    const float* __restrict__ f_w, const float* __restrict__ f_b,
    const float* __restrict__ o_w, const float* __restrict__ o_b,
    const float* __restrict__ m_in, float* __restrict__ m_out,
    const float* __restrict__ c, const float* __restrict__ n,
    const float* __restrict__ gn_w, const float* __restrict__ gn_b,
    float* __restrict__ c_new, float* __restrict__ n_new) {
    __shared__ float s_xc[DM];
    __shared__ float s_in[DM];
    __shared__ float sg_i[NHD], sg_f[NHD], sg_o[NHD];

    const int b = blockIdx.x;
    const int t = threadIdx.x;
    const int h = t >> 5;
    const int lane = t & 31;

    // stage rows (float4; 256 thr x 4 = 1024)
    *(float4*)&s_xc[t * 4] = *(const float4*)&g_xconv[(size_t)b * DM + t * 4];
    *(float4*)&s_in[t * 4] = *(const float4*)&inp[(size_t)b * DM + t * 4];
    __syncthreads();

    // ---- phase 1: gate dots (warp h -> head h), float4 ----
    {
        const float* iw = &i_w[h * DM];
        const float* fw = &f_w[h * DM];
        const float* ow = &o_w[h * DM];
        float di = 0.f, df = 0.f, dz = 0.f;
#pragma unroll
        for (int it = 0; it < 8; it++) {
            int k = it * 128 + lane * 4;
            float4 x = *(const float4*)&s_xc[k];
            float4 y = *(const float4*)&s_in[k];
            float4 wi = *(const float4*)&iw[k];
            float4 wf = *(const float4*)&fw[k];
            float4 wo = *(const float4*)&ow[k];
            di += x.x * wi.x + x.y * wi.y + x.z * wi.z + x.w * wi.w;
            df += x.x * wf.x + x.y * wf.y + x.z * wf.z + x.w * wf.w;
            dz += y.x * wo.x + y.y * wo.y + y.z * wo.z + y.w * wo.w;
        }
#pragma unroll
        for (int off = 16; off > 0; off >>= 1) {
            di += __shfl_down_sync(0xffffffffu, di, off);
            df += __shfl_down_sync(0xffffffffu, df, off);
            dz += __shfl_down_sync(0xffffffffu, dz, off);
        }
        if (lane == 0) {
            float it = softcap_f(di + i_b[h]);
            float ft = softcap_f(df + f_b[h]);
            float ot = softcap_f(dz + o_b[h]);
            float flog = -log1pf(expf(-ft));
            float mv   = m_in[b * NHD + h];
            float mn   = fmaxf(flog + mv, it);
            sg_i[h] = expf(it - mn);
            sg_f[h] = expf(flog + mv - mn);
            sg_o[h] = 1.0f / (1.0f + expf(-ot));
            m_out[b * NHD + h] = mn;
        }
    }
    __syncthreads();

    // ---- phase 2: cell update + LN (warp h -> head h, 4 elems/lane) ----
    {
        const float ig = sg_i[h];
        const float fg = sg_f[h];
        const float og = sg_o[h];
        const int e = lane * 4;
        const int col = h * HD + e;
        const size_t base = (size_t)(b * NHD + h) * HD + e;

        float4 c4 = *(const float4*)&c[base];
        float4 n4 = *(const float4*)&n[base];
        float4 z4 = *(const float4*)&g_z[(size_t)b * HIDM + col];

        float cv[4], nv[4], hv[4];
        cv[0] = fg * c4.x + ig * z4.x; cv[1] = fg * c4.y + ig * z4.y;
        cv[2] = fg * c4.z + ig * z4.z; cv[3] = fg * c4.w + ig * z4.w;
        nv[0] = fg * n4.x + ig; nv[1] = fg * n4.y + ig;
        nv[2] = fg * n4.z + ig; nv[3] = fg * n4.w + ig;
#pragma unroll
        for (int j = 0; j < 4; j++) hv[j] = og * cv[j] / (nv[j] + EPSV);

        *(float4*)&c_new[base] = *(float4*)cv;
        *(float4*)&n_new[base] = *(float4*)nv;

        float s = hv[0] + hv[1] + hv[2] + hv[3];
        float s2 = hv[0] * hv[0] + hv[1] * hv[1] + hv[2] * hv[2] + hv[3] * hv[3];
#pragma unroll
        for (int off = 16; off > 0; off >>= 1) {
            s  += __shfl_xor_sync(0xffffffffu, s, off);
            s2 += __shfl_xor_sync(0xffffffffu, s2, off);
        }
        float mu  = s * (1.0f / HD);
        float var = s2 * (1.0f / HD) - mu * mu;
        float rs  = rsqrtf(var + EPSV);

        float4 gw = *(const float4*)&gn_w[col];
        float4 gb = *(const float4*)&gn_b[col];
        float hn[4];
        hn[0] = (hv[0] - mu) * rs * gw.x + gb.x;
        hn[1] = (hv[1] - mu) * rs * gw.y + gb.y;
        hn[2] = (hv[2] - mu) * rs * gw.z + gb.z;
        hn[3] = (hv[3] - mu) * rs * gw.w + gb.w;

        __nv_bfloat162 hp0, hp1, lp0, lp1;
        hp0.x = __float2bfloat16(hn[0]); hp0.y = __float2bfloat16(hn[1]);
        hp1.x = __float2bfloat16(hn[2]); hp1.y = __float2bfloat16(hn[3]);
        lp0.x = __float2bfloat16(hn[0] - __bfloat162float(hp0.x));
        lp0.y = __float2bfloat16(hn[1] - __bfloat162float(hp0.y));
        lp1.x = __float2bfloat16(hn[2] - __bfloat162float(hp1.x));
        lp1.y = __float2bfloat16(hn[3] - __bfloat162float(hp1.y));
        uint2 hu, lu;
        hu.x = *(uint32_t*)&hp0; hu.y = *(uint32_t*)&hp1;
        lu.x = *(uint32_t*)&lp0; lu.y = *(uint32_t*)&lp1;

        int mtile = b >> 7, r = b & 127, kc = col >> 6;
        size_t off = ((size_t)(mtile * 16 + kc)) * CHUNK_A +
                     swz128((uint32_t)r * 128 + (uint32_t)(col & 63) * 2);
        *(uint2*)((char*)g_Hhi + off) = hu;
        *(uint2*)((char*)g_Hlo + off) = lu;
    }
}

// ---------------- launch ------------------------------------------
extern "C" void kernel_launch(void* const* d_in, const int* in_sizes, int n_in,
                              void* d_out, int out_size) {
    const float* inputs = (const float*)d_in[0];
    const float* c      = (const float*)d_in[1];
    const float* n      = (const float*)d_in[2];
    const float* m      = (const float*)d_in[3];
    const float* conv_w = (const float*)d_in[4];
    const float* conv_b = (const float*)d_in[5];
    const float* z_w    = (const float*)d_in[6];
    const float* i_w    = (const float*)d_in[7];
    const float* i_b    = (const float*)d_in[8];
    const float* f_w    = (const float*)d_in[9];
    const float* f_b    = (const float*)d_in[10];
    const float* o_w    = (const float*)d_in[11];
    const float* o_b    = (const float*)d_in[12];
    const float* gn_w   = (const float*)d_in[13];
    const float* gn_b   = (const float*)d_in[14];
    const float* out_w  = (const float*)d_in[15];

    float* out   = (float*)d_out;
    float* c_new = out + (size_t)BSZ * DM;
    float* n_new = c_new + (size_t)BSZ * NHD * HD;
    float* m_new = n_new + (size_t)BSZ * NHD * HD;

    cudaFuncSetAttribute(hmma_gemm_kernel<0>, cudaFuncAttributeMaxDynamicSharedMemorySize, SMEM_TOTAL);
    cudaFuncSetAttribute(hmma_gemm_kernel<1>, cudaFuncAttributeMaxDynamicSharedMemorySize, SMEM_TOTAL);

    // 1) pack weights
    pack_w_kernel<<<(3072 * 512 + 255) / 256, 256>>>(conv_w, z_w, out_w);

    // 2) convert inputs to blocked bf16 hi/lo
    conv_in_kernel<<<BSZ, 256>>>(inputs);

    // 3) GEMM1: [xconv | z]
    hmma_gemm_kernel<0><<<dim3(8, BSZ / TM), 288, SMEM_TOTAL>>>(conv_b, nullptr);

    // 4) fused gates + cell update + LN (emits h_norm bf16 hi/lo blocked)
    gact_kernel<<<BSZ, 256>>>(inputs, i_w, i_b, f_w, f_b, o_w, o_b, m, m_new,
                              c, n, gn_w, gn_b, c_new, n_new);

    // 5) GEMM2: out = h_norm @ out_w^T
    hmma_gemm_kernel<1><<<dim3(4, BSZ / TM), 288, SMEM_TOTAL>>>(nullptr, out);
}